// round 2
// baseline (speedup 1.0000x reference)
#include <cuda_runtime.h>

#define Bn 1024
#define Ln 50
#define Dn 64
#define Sn 2
#define XS 65      // row stride (floats) for L x D activation arrays (odd -> conflict-free column access)
#define SCS 52     // row stride for the 50x50 score matrix
#define NT 256
#define NEGV -4294967296.0f   // float(-2**32+1) after fp32 rounding (matches JAX)

// ---- shared memory layout (float offsets) ----
#define O_IN    0       // inputs (post-LN), kept for LBA head      50*65 -> 3264
#define O_X     3264    // running x
#define O_B1    6528    // Qx / Kx_lba / h
#define O_B2    9792    // Kx / Vx_lba
#define O_B3    13056   // Vx
#define O_ATT   16320   // att
#define O_WS    19584   // weight staging (64x64 or 50x50)          4096
#define O_SC    23680   // scores 50x52                              2608
#define O_PM    26288   // padding mask (64)
#define O_QV    26352   // query vector (64)
#define O_SCQ   26416   // lba scores / softmax probs (64)
#define O_GLO   26480   // glo (64)
#define O_GFIN  26544   // final glo (64)
#define O_GW    26608   // gated_weight (192)
#define O_AIE   26800   // dot(ie, w0) per row (64)
#define O_MISC  26864   // scalars (16)
#define SMEM_FLOATS 26880

__device__ __forceinline__ float wredsum(float v) {
#pragma unroll
    for (int o = 16; o; o >>= 1) v += __shfl_xor_sync(0xffffffffu, v, o);
    return v;
}
__device__ __forceinline__ float wredmax(float v) {
#pragma unroll
    for (int o = 16; o; o >>= 1) v = fmaxf(v, __shfl_xor_sync(0xffffffffu, v, o));
    return v;
}
__device__ __forceinline__ float sigm(float x) { return 1.0f / (1.0f + expf(-x)); }

// in-place LayerNorm of each row (L rows, D cols, stride XS); one warp per row
__device__ __forceinline__ void ln_rows(float* m, int warp, int lane) {
    for (int l = warp; l < Ln; l += 8) {
        float v0 = m[l * XS + lane], v1 = m[l * XS + lane + 32];
        float mu = wredsum(v0 + v1) * (1.0f / Dn);
        v0 -= mu; v1 -= mu;
        float var = wredsum(v0 * v0 + v1 * v1) * (1.0f / Dn);
        float inv = rsqrtf(var + 1e-8f);
        m[l * XS + lane] = v0 * inv;
        m[l * XS + lane + 32] = v1 * inv;
    }
}

// out(LxD, stride XS) = xin(LxD, stride XS) @ w(DxD, row-major stride Dn)
// 2 rows x 4 cols per thread-tile
__device__ __forceinline__ void gemm_xw(float* out, const float* xin, const float* w, int tid) {
    for (int t = tid; t < 400; t += NT) {
        int rp = t >> 4, c4 = t & 15;
        int l0 = rp * 2;
        const float* x0 = xin + l0 * XS;
        const float* x1 = x0 + XS;
        float a0 = 0, a1 = 0, a2 = 0, a3 = 0, b0 = 0, b1 = 0, b2 = 0, b3 = 0;
#pragma unroll 8
        for (int k = 0; k < Dn; k++) {
            float4 wv = *(const float4*)(w + k * Dn + c4 * 4);
            float xa = x0[k], xb = x1[k];
            a0 += xa * wv.x; a1 += xa * wv.y; a2 += xa * wv.z; a3 += xa * wv.w;
            b0 += xb * wv.x; b1 += xb * wv.y; b2 += xb * wv.z; b3 += xb * wv.w;
        }
        float* o0 = out + l0 * XS + c4 * 4;
        o0[0] = a0; o0[1] = a1; o0[2] = a2; o0[3] = a3;
        float* o1 = o0 + XS;
        o1[0] = b0; o1[1] = b1; o1[2] = b2; o1[3] = b3;
    }
}

__device__ __forceinline__ void load_sm(float* dst, const float* src, int n, int tid) {
    for (int i = tid; i < n; i += NT) dst[i] = src[i];
}

__global__ void __launch_bounds__(NT, 2) fissa_kernel(
    const int* __restrict__ user_items, const int* __restrict__ pos_items,
    const int* __restrict__ neg_items, const float* __restrict__ padding_mask,
    const float* __restrict__ item_embedding, const float* __restrict__ pos_embedding,
    const float* __restrict__ Q_sabs, const float* __restrict__ K_sabs,
    const float* __restrict__ V_sabs, const float* __restrict__ c1_w,
    const float* __restrict__ c1_b, const float* __restrict__ c2_w,
    const float* __restrict__ c2_b, const float* __restrict__ query_item,
    const float* __restrict__ K_lba, const float* __restrict__ V_lba,
    const float* __restrict__ l1_w, const float* __restrict__ l1_b,
    const float* __restrict__ l2_w, const float* __restrict__ l2_b,
    const float* __restrict__ gated_weight, const float* __restrict__ gated_bias,
    float* __restrict__ out)
{
    extern __shared__ float sm[];
    float* s_in  = sm + O_IN;
    float* s_x   = sm + O_X;
    float* s_b1  = sm + O_B1;
    float* s_b2  = sm + O_B2;
    float* s_b3  = sm + O_B3;
    float* s_att = sm + O_ATT;
    float* s_ws  = sm + O_WS;
    float* s_sc  = sm + O_SC;
    float* s_pm  = sm + O_PM;
    float* s_qv  = sm + O_QV;
    float* s_scq = sm + O_SCQ;
    float* s_glo = sm + O_GLO;
    float* s_gf  = sm + O_GFIN;
    float* s_gw  = sm + O_GW;
    float* s_aie = sm + O_AIE;
    float* s_ms  = sm + O_MISC;

    const int b = blockIdx.x;
    const int tid = threadIdx.x;
    const int lane = tid & 31;
    const int warp = tid >> 5;

    if (tid < Ln)  s_pm[tid] = padding_mask[b * Ln + tid];
    if (tid < Dn)  s_qv[tid] = query_item[tid];
    if (tid < 192) s_gw[tid] = gated_weight[tid];
    __syncthreads();

    // ---- embed + pos + mask + LN -> inputs, x ----
    for (int l = warp; l < Ln; l += 8) {
        int idx = user_items[b * Ln + l];
        float v0 = item_embedding[idx * Dn + lane]      + pos_embedding[l * Dn + lane];
        float v1 = item_embedding[idx * Dn + lane + 32] + pos_embedding[l * Dn + lane + 32];
        float pmv = s_pm[l];
        v0 *= pmv; v1 *= pmv;
        float mu = wredsum(v0 + v1) * (1.0f / Dn);
        v0 -= mu; v1 -= mu;
        float var = wredsum(v0 * v0 + v1 * v1) * (1.0f / Dn);
        float inv = rsqrtf(var + 1e-8f);
        v0 *= inv; v1 *= inv;
        s_in[l * XS + lane] = v0;       s_in[l * XS + lane + 32] = v1;
        s_x [l * XS + lane] = v0;       s_x [l * XS + lane + 32] = v1;
    }
    __syncthreads();

    // ---- transformer layers ----
    for (int s = 0; s < Sn; s++) {
        load_sm(s_ws, Q_sabs + s * Dn * Dn, Dn * Dn, tid); __syncthreads();
        gemm_xw(s_b1, s_x, s_ws, tid);                      __syncthreads();
        load_sm(s_ws, K_sabs + s * Dn * Dn, Dn * Dn, tid); __syncthreads();
        gemm_xw(s_b2, s_x, s_ws, tid);                      __syncthreads();
        load_sm(s_ws, V_sabs + s * Dn * Dn, Dn * Dn, tid); __syncthreads();
        gemm_xw(s_b3, s_x, s_ws, tid);                      __syncthreads();

        // scores[q][k] = dot(Qx[q],Kx[k])/8, causal/key mask, * pm[q]
        for (int t = tid; t < 13 * Ln; t += NT) {
            int qp = t / Ln;
            int k  = t % Ln;
            int q0 = qp * 4;
            const float* Kr = s_b2 + k * XS;
            const float* Q0 = s_b1 + q0 * XS;
            float a0 = 0, a1 = 0, a2 = 0, a3 = 0;
#pragma unroll 8
            for (int d = 0; d < Dn; d++) {
                float kv = Kr[d];
                a0 += Q0[d] * kv;
                a1 += Q0[XS + d] * kv;
                a2 += Q0[2 * XS + d] * kv;
                a3 += Q0[3 * XS + d] * kv;
            }
            float acc[4] = {a0, a1, a2, a3};
            float pmk = s_pm[k];
#pragma unroll
            for (int j = 0; j < 4; j++) {
                int q = q0 + j;
                if (q < Ln) {
                    float v = acc[j] * 0.125f;
                    if (k > q) v = NEGV;
                    if (pmk == 0.0f) v = NEGV;
                    v *= s_pm[q];
                    s_sc[q * SCS + k] = v;
                }
            }
        }
        __syncthreads();

        // att = scores @ Vx + x  -> s_att, then LN
        for (int t = tid; t < 400; t += NT) {
            int rp = t >> 4, c4 = t & 15;
            int q0 = rp * 2, d0 = c4 * 4;
            float a00 = 0, a01 = 0, a02 = 0, a03 = 0, a10 = 0, a11 = 0, a12 = 0, a13 = 0;
#pragma unroll 5
            for (int k = 0; k < Ln; k++) {
                float w0 = s_sc[q0 * SCS + k];
                float w1 = s_sc[(q0 + 1) * SCS + k];
                const float* v = s_b3 + k * XS + d0;
                float v0 = v[0], v1 = v[1], v2 = v[2], v3 = v[3];
                a00 += w0 * v0; a01 += w0 * v1; a02 += w0 * v2; a03 += w0 * v3;
                a10 += w1 * v0; a11 += w1 * v1; a12 += w1 * v2; a13 += w1 * v3;
            }
            float* o0 = s_att + q0 * XS + d0;
            const float* x0 = s_x + q0 * XS + d0;
            o0[0] = a00 + x0[0]; o0[1] = a01 + x0[1]; o0[2] = a02 + x0[2]; o0[3] = a03 + x0[3];
            float* o1 = o0 + XS;  const float* x1 = x0 + XS;
            o1[0] = a10 + x1[0]; o1[1] = a11 + x1[1]; o1[2] = a12 + x1[2]; o1[3] = a13 + x1[3];
        }
        __syncthreads();
        ln_rows(s_att, warp, lane);
        __syncthreads();

        // h = relu(c1_w @ att + c1_b) -> b1
        load_sm(s_ws, c1_w + s * Ln * Ln, Ln * Ln, tid); __syncthreads();
        for (int t = tid; t < 400; t += NT) {
            int rp = t >> 4, c4 = t & 15;
            int l0 = rp * 2, d0 = c4 * 4;
            float a00 = 0, a01 = 0, a02 = 0, a03 = 0, a10 = 0, a11 = 0, a12 = 0, a13 = 0;
#pragma unroll 5
            for (int j = 0; j < Ln; j++) {
                float w0 = s_ws[l0 * Ln + j];
                float w1 = s_ws[(l0 + 1) * Ln + j];
                const float* v = s_att + j * XS + d0;
                float v0 = v[0], v1 = v[1], v2 = v[2], v3 = v[3];
                a00 += w0 * v0; a01 += w0 * v1; a02 += w0 * v2; a03 += w0 * v3;
                a10 += w1 * v0; a11 += w1 * v1; a12 += w1 * v2; a13 += w1 * v3;
            }
            float cb0 = c1_b[s * Ln + l0], cb1 = c1_b[s * Ln + l0 + 1];
            float* o0 = s_b1 + l0 * XS + d0;
            o0[0] = fmaxf(a00 + cb0, 0.f); o0[1] = fmaxf(a01 + cb0, 0.f);
            o0[2] = fmaxf(a02 + cb0, 0.f); o0[3] = fmaxf(a03 + cb0, 0.f);
            float* o1 = o0 + XS;
            o1[0] = fmaxf(a10 + cb1, 0.f); o1[1] = fmaxf(a11 + cb1, 0.f);
            o1[2] = fmaxf(a12 + cb1, 0.f); o1[3] = fmaxf(a13 + cb1, 0.f);
        }
        __syncthreads();

        // ff = c2_w @ h + c2_b + att, * pm -> x, then LN
        load_sm(s_ws, c2_w + s * Ln * Ln, Ln * Ln, tid); __syncthreads();
        for (int t = tid; t < 400; t += NT) {
            int rp = t >> 4, c4 = t & 15;
            int l0 = rp * 2, d0 = c4 * 4;
            float a00 = 0, a01 = 0, a02 = 0, a03 = 0, a10 = 0, a11 = 0, a12 = 0, a13 = 0;
#pragma unroll 5
            for (int j = 0; j < Ln; j++) {
                float w0 = s_ws[l0 * Ln + j];
                float w1 = s_ws[(l0 + 1) * Ln + j];
                const float* v = s_b1 + j * XS + d0;
                float v0 = v[0], v1 = v[1], v2 = v[2], v3 = v[3];
                a00 += w0 * v0; a01 += w0 * v1; a02 += w0 * v2; a03 += w0 * v3;
                a10 += w1 * v0; a11 += w1 * v1; a12 += w1 * v2; a13 += w1 * v3;
            }
            float cb0 = c2_b[s * Ln + l0], cb1 = c2_b[s * Ln + l0 + 1];
            float pm0 = s_pm[l0], pm1 = s_pm[l0 + 1];
            const float* at0 = s_att + l0 * XS + d0;
            float* o0 = s_x + l0 * XS + d0;
            o0[0] = (a00 + cb0 + at0[0]) * pm0; o0[1] = (a01 + cb0 + at0[1]) * pm0;
            o0[2] = (a02 + cb0 + at0[2]) * pm0; o0[3] = (a03 + cb0 + at0[3]) * pm0;
            const float* at1 = at0 + XS;
            float* o1 = o0 + XS;
            o1[0] = (a10 + cb1 + at1[0]) * pm1; o1[1] = (a11 + cb1 + at1[1]) * pm1;
            o1[2] = (a12 + cb1 + at1[2]) * pm1; o1[3] = (a13 + cb1 + at1[3]) * pm1;
        }
        __syncthreads();
        ln_rows(s_x, warp, lane);
        __syncthreads();
    }

    // ---- LBA head: Kx = inputs @ K_lba, Vx = inputs @ V_lba ----
    load_sm(s_ws, K_lba, Dn * Dn, tid); __syncthreads();
    gemm_xw(s_b1, s_in, s_ws, tid);      __syncthreads();
    load_sm(s_ws, V_lba, Dn * Dn, tid); __syncthreads();
    gemm_xw(s_b2, s_in, s_ws, tid);      __syncthreads();

    // sc[l] = dot(query, Kx[l]); key-mask
    for (int l = warp; l < Ln; l += 8) {
        float r = s_qv[lane] * s_b1[l * XS + lane] + s_qv[lane + 32] * s_b1[l * XS + lane + 32];
        r = wredsum(r);
        if (s_pm[l] == 0.0f) r = NEGV;
        if (lane == 0) s_scq[l] = r;
    }
    __syncthreads();

    // softmax over L (warp 0)
    if (warp == 0) {
        float v0 = (lane < Ln) ? s_scq[lane] : -3.4e38f;
        float v1 = (lane + 32 < Ln) ? s_scq[lane + 32] : -3.4e38f;
        float m = wredmax(fmaxf(v0, v1));
        float e0 = (lane < Ln) ? expf(v0 - m) : 0.0f;
        float e1 = (lane + 32 < Ln) ? expf(v1 - m) : 0.0f;
        float ssum = wredsum(e0 + e1);
        float inv = 1.0f / ssum;
        if (lane < Ln) s_scq[lane] = e0 * inv;
        if (lane + 32 < Ln) s_scq[lane + 32] = e1 * inv;
    }
    __syncthreads();

    // glo[d] = sum_l p[l] * Vx[l][d]
    if (tid < Dn) {
        float a = 0.0f;
#pragma unroll 5
        for (int l = 0; l < Ln; l++) a += s_scq[l] * s_b2[l * XS + tid];
        s_glo[tid] = a;
    }
    __syncthreads();

    // LN -> MLP -> residual -> LN -> gfin; a_glo = dot(gfin, w1)+bias (warp 0)
    if (warp == 0) {
        float g0 = s_glo[lane], g1 = s_glo[lane + 32];
        float mu = wredsum(g0 + g1) * (1.0f / Dn);
        g0 -= mu; g1 -= mu;
        float var = wredsum(g0 * g0 + g1 * g1) * (1.0f / Dn);
        float inv = rsqrtf(var + 1e-8f);
        g0 *= inv; g1 *= inv;
        float w1v = l1_w[0], b1v = l1_b[0], w2v = l2_w[0], b2v = l2_b[0];
        float h0 = fmaxf(w1v * g0 + b1v, 0.0f);
        float h1 = fmaxf(w1v * g1 + b1v, 0.0f);
        float f0 = w2v * h0 + b2v + g0;
        float f1 = w2v * h1 + b2v + g1;
        mu = wredsum(f0 + f1) * (1.0f / Dn);
        f0 -= mu; f1 -= mu;
        var = wredsum(f0 * f0 + f1 * f1) * (1.0f / Dn);
        inv = rsqrtf(var + 1e-8f);
        f0 *= inv; f1 *= inv;
        s_gf[lane] = f0; s_gf[lane + 32] = f1;
        float r = wredsum(f0 * s_gw[64 + lane] + f1 * s_gw[96 + lane]);
        if (lane == 0) s_ms[0] = r + gated_bias[0];
    }

    // a_ie[l] = dot(ie_raw[l], w0)
    for (int l = warp; l < Ln; l += 8) {
        int idx = user_items[b * Ln + l];
        float r = item_embedding[idx * Dn + lane] * s_gw[lane]
                + item_embedding[idx * Dn + lane + 32] * s_gw[lane + 32];
        r = wredsum(r);
        if (lane == 0) s_aie[l] = r;
    }
    __syncthreads();

    // ---- gating + output LN + dot with pos_e / neg_e ----
    float base_glo = s_ms[0];
    float gf0 = s_gf[lane], gf1 = s_gf[lane + 32];
    for (int l = warp; l < Ln; l += 8) {
        float xv0 = s_x[l * XS + lane], xv1 = s_x[l * XS + lane + 32];
        float pmv = s_pm[l];
        float base = s_aie[l] + base_glo;
#pragma unroll
        for (int br = 0; br < 2; br++) {
            const int* items = br ? neg_items : pos_items;
            int idx = items[b * Ln + l];
            float m0 = item_embedding[idx * Dn + lane];
            float m1 = item_embedding[idx * Dn + lane + 32];
            float dm = wredsum(m0 * s_gw[128 + lane] + m1 * s_gw[160 + lane]);
            float logit = base + dm;
            float g = sigm(sigm(logit));
            float o0 = (xv0 * g + gf0 * (1.0f - g)) * pmv;
            float o1 = (xv1 * g + gf1 * (1.0f - g)) * pmv;
            float mu = wredsum(o0 + o1) * (1.0f / Dn);
            o0 -= mu; o1 -= mu;
            float var = wredsum(o0 * o0 + o1 * o1) * (1.0f / Dn);
            float inv = rsqrtf(var + 1e-8f);
            float r = wredsum((o0 * m0 + o1 * m1) * inv);
            if (lane == 0) out[br * (Bn * Ln) + b * Ln + l] = r;
        }
    }
}

extern "C" void kernel_launch(void* const* d_in, const int* in_sizes, int n_in,
                              void* d_out, int out_size) {
    const int*   user_items     = (const int*)d_in[0];
    const int*   pos_items      = (const int*)d_in[1];
    const int*   neg_items      = (const int*)d_in[2];
    const float* padding_mask   = (const float*)d_in[3];
    const float* item_embedding = (const float*)d_in[4];
    const float* pos_embedding  = (const float*)d_in[5];
    const float* Q_sabs         = (const float*)d_in[6];
    const float* K_sabs         = (const float*)d_in[7];
    const float* V_sabs         = (const float*)d_in[8];
    const float* c1_w           = (const float*)d_in[9];
    const float* c1_b           = (const float*)d_in[10];
    const float* c2_w           = (const float*)d_in[11];
    const float* c2_b           = (const float*)d_in[12];
    const float* query_item     = (const float*)d_in[13];
    const float* K_lba          = (const float*)d_in[14];
    const float* V_lba          = (const float*)d_in[15];
    const float* l1_w           = (const float*)d_in[16];
    const float* l1_b           = (const float*)d_in[17];
    const float* l2_w           = (const float*)d_in[18];
    const float* l2_b           = (const float*)d_in[19];
    const float* gated_weight   = (const float*)d_in[20];
    const float* gated_bias     = (const float*)d_in[21];

    size_t smem = SMEM_FLOATS * sizeof(float);
    cudaFuncSetAttribute(fissa_kernel, cudaFuncAttributeMaxDynamicSharedMemorySize, (int)smem);
    fissa_kernel<<<Bn, NT, smem>>>(
        user_items, pos_items, neg_items, padding_mask, item_embedding, pos_embedding,
        Q_sabs, K_sabs, V_sabs, c1_w, c1_b, c2_w, c2_b, query_item, K_lba, V_lba,
        l1_w, l1_b, l2_w, l2_b, gated_weight, gated_bias, (float*)d_out);
}

// round 3
// speedup vs baseline: 1.1723x; 1.1723x over previous
#include <cuda_runtime.h>

#define Bn 1024
#define Ln 50
#define Lp 52      // padded row count
#define Dn 64
#define Sn 2
#define XS 68      // row stride (floats) for Lp x D activation arrays (16B-aligned, 4*XS%32==16)
#define SCS 52     // row stride for the padded 52x52 score matrix
#define NT 256
#define NEGV -4294967296.0f   // float(-2**32+1) after fp32 rounding (matches JAX)

// ---- shared memory layout (float offsets) ----
#define O_IN    0                    // inputs (post-LN), kept for LBA head  52*68=3536
#define O_X     3536                 // running x
#define O_B1    7072                 // Qx -> h -> Kx_lba
#define O_B2    10608                // Kx -> att -> Vx_lba
#define O_B3    14144                // Vx
#define O_WS    17680                // weight staging (64x64 or padded 52x52)  4096
#define O_SC    21776                // scores 52x52                            2704
#define O_CB    24480                // staged bias (52)
#define O_PM    24532                // padding mask (52)
#define O_QV    24584                // query vector (64)
#define O_SCQ   24648                // lba scores / softmax probs (64)
#define O_GLO   24712                // glo (64)
#define O_GFIN  24776                // final glo (64)
#define O_GW    24840                // gated_weight (192)
#define O_AIE   25032                // dot(ie, w0) per row (52->56)
#define O_MISC  25088                // scalars (16)
#define SMEM_FLOATS 25104            // ~100.4 KB -> 2 CTAs/SM

__device__ __forceinline__ float wredsum(float v) {
#pragma unroll
    for (int o = 16; o; o >>= 1) v += __shfl_xor_sync(0xffffffffu, v, o);
    return v;
}
__device__ __forceinline__ float wredmax(float v) {
#pragma unroll
    for (int o = 16; o; o >>= 1) v = fmaxf(v, __shfl_xor_sync(0xffffffffu, v, o));
    return v;
}
__device__ __forceinline__ float sigm(float x) { return 1.0f / (1.0f + expf(-x)); }

// in-place LayerNorm of rows 0..49 (D cols, stride XS); one warp per row
__device__ __forceinline__ void ln_rows(float* m, int warp, int lane) {
    for (int l = warp; l < Ln; l += 8) {
        float v0 = m[l * XS + lane], v1 = m[l * XS + lane + 32];
        float mu = wredsum(v0 + v1) * (1.0f / Dn);
        v0 -= mu; v1 -= mu;
        float var = wredsum(v0 * v0 + v1 * v1) * (1.0f / Dn);
        float inv = rsqrtf(var + 1e-8f);
        m[l * XS + lane] = v0 * inv;
        m[l * XS + lane + 32] = v1 * inv;
    }
}

// out(Lp x D, stride XS) = xin(Lp x D, stride XS) @ w(DxD, row-major stride Dn)
// 4 rows x 4 cols per thread, 4-deep k unroll, all LDS.128.
__device__ __forceinline__ void gemm44_xw(float* __restrict__ out, const float* __restrict__ xin,
                                          const float* __restrict__ w, int tid) {
    if (tid < 208) {                 // 13 row-blocks x 16 col-blocks
        int rp = tid >> 4, c4 = tid & 15;
        const float* x0 = xin + rp * 4 * XS;
        float a[4][4];
#pragma unroll
        for (int j = 0; j < 4; j++)
#pragma unroll
            for (int i = 0; i < 4; i++) a[j][i] = 0.0f;
#pragma unroll 4
        for (int k4 = 0; k4 < 16; k4++) {
            float4 xv[4];
#pragma unroll
            for (int j = 0; j < 4; j++)
                xv[j] = *(const float4*)(x0 + j * XS + k4 * 4);
#pragma unroll
            for (int kk = 0; kk < 4; kk++) {
                float4 wv = *(const float4*)(w + (k4 * 4 + kk) * Dn + c4 * 4);
#pragma unroll
                for (int j = 0; j < 4; j++) {
                    float xk = ((const float*)&xv[j])[kk];
                    a[j][0] += xk * wv.x; a[j][1] += xk * wv.y;
                    a[j][2] += xk * wv.z; a[j][3] += xk * wv.w;
                }
            }
        }
#pragma unroll
        for (int j = 0; j < 4; j++) {
            *(float4*)(out + (rp * 4 + j) * XS + c4 * 4) =
                make_float4(a[j][0], a[j][1], a[j][2], a[j][3]);
        }
    }
}

// core: acc += A(4 rows, stride astr, inner 52) x B(52 x D, stride XS), cols c4*4..+3
__device__ __forceinline__ void core52(const float* __restrict__ A0, int astr,
                                       const float* __restrict__ Bm, int c4, float a[4][4]) {
#pragma unroll 4
    for (int k4 = 0; k4 < 13; k4++) {
        float4 wv[4];
#pragma unroll
        for (int j = 0; j < 4; j++)
            wv[j] = *(const float4*)(A0 + j * astr + k4 * 4);
#pragma unroll
        for (int kk = 0; kk < 4; kk++) {
            float4 bv = *(const float4*)(Bm + (k4 * 4 + kk) * XS + c4 * 4);
#pragma unroll
            for (int j = 0; j < 4; j++) {
                float wk = ((const float*)&wv[j])[kk];
                a[j][0] += wk * bv.x; a[j][1] += wk * bv.y;
                a[j][2] += wk * bv.z; a[j][3] += wk * bv.w;
            }
        }
    }
}

__device__ __forceinline__ void load_sm(float* dst, const float* src, int n, int tid) {
    for (int i = tid; i < n; i += NT) dst[i] = src[i];
}

// stage 50x50 weight -> 52x52 zero-padded, plus 50-entry bias -> 52 padded
__device__ __forceinline__ void stage_w52(float* dst, const float* src,
                                          float* cb_dst, const float* cb_src, int tid) {
    for (int i = tid; i < Lp * Lp; i += NT) {
        int r = i / Lp, c = i % Lp;
        dst[i] = (r < Ln && c < Ln) ? src[r * Ln + c] : 0.0f;
    }
    if (tid < Lp) cb_dst[tid] = (tid < Ln) ? cb_src[tid] : 0.0f;
}

__global__ void __launch_bounds__(NT, 2) fissa_kernel(
    const int* __restrict__ user_items, const int* __restrict__ pos_items,
    const int* __restrict__ neg_items, const float* __restrict__ padding_mask,
    const float* __restrict__ item_embedding, const float* __restrict__ pos_embedding,
    const float* __restrict__ Q_sabs, const float* __restrict__ K_sabs,
    const float* __restrict__ V_sabs, const float* __restrict__ c1_w,
    const float* __restrict__ c1_b, const float* __restrict__ c2_w,
    const float* __restrict__ c2_b, const float* __restrict__ query_item,
    const float* __restrict__ K_lba, const float* __restrict__ V_lba,
    const float* __restrict__ l1_w, const float* __restrict__ l1_b,
    const float* __restrict__ l2_w, const float* __restrict__ l2_b,
    const float* __restrict__ gated_weight, const float* __restrict__ gated_bias,
    float* __restrict__ out)
{
    extern __shared__ float sm[];
    float* s_in  = sm + O_IN;
    float* s_x   = sm + O_X;
    float* s_b1  = sm + O_B1;
    float* s_b2  = sm + O_B2;
    float* s_b3  = sm + O_B3;
    float* s_ws  = sm + O_WS;
    float* s_sc  = sm + O_SC;
    float* s_cb  = sm + O_CB;
    float* s_pm  = sm + O_PM;
    float* s_qv  = sm + O_QV;
    float* s_scq = sm + O_SCQ;
    float* s_glo = sm + O_GLO;
    float* s_gf  = sm + O_GFIN;
    float* s_gw  = sm + O_GW;
    float* s_aie = sm + O_AIE;
    float* s_ms  = sm + O_MISC;

    const int b = blockIdx.x;
    const int tid = threadIdx.x;
    const int lane = tid & 31;
    const int warp = tid >> 5;

    if (tid < Lp)  s_pm[tid] = (tid < Ln) ? padding_mask[b * Ln + tid] : 0.0f;
    if (tid < Dn)  s_qv[tid] = query_item[tid];
    if (tid < 192) s_gw[tid] = gated_weight[tid];
    // zero padded rows 50,51 of s_in and s_x
    if (tid < 2 * XS) { s_in[Ln * XS + tid] = 0.0f; s_x[Ln * XS + tid] = 0.0f; }
    __syncthreads();

    // ---- embed + pos + mask + LN -> inputs, x ----
    for (int l = warp; l < Ln; l += 8) {
        int idx = user_items[b * Ln + l];
        float v0 = item_embedding[idx * Dn + lane]      + pos_embedding[l * Dn + lane];
        float v1 = item_embedding[idx * Dn + lane + 32] + pos_embedding[l * Dn + lane + 32];
        float pmv = s_pm[l];
        v0 *= pmv; v1 *= pmv;
        float mu = wredsum(v0 + v1) * (1.0f / Dn);
        v0 -= mu; v1 -= mu;
        float var = wredsum(v0 * v0 + v1 * v1) * (1.0f / Dn);
        float inv = rsqrtf(var + 1e-8f);
        v0 *= inv; v1 *= inv;
        s_in[l * XS + lane] = v0;       s_in[l * XS + lane + 32] = v1;
        s_x [l * XS + lane] = v0;       s_x [l * XS + lane + 32] = v1;
    }
    __syncthreads();

    // ---- transformer layers ----
    for (int s = 0; s < Sn; s++) {
        load_sm(s_ws, Q_sabs + s * Dn * Dn, Dn * Dn, tid); __syncthreads();
        gemm44_xw(s_b1, s_x, s_ws, tid);                    __syncthreads();
        load_sm(s_ws, K_sabs + s * Dn * Dn, Dn * Dn, tid); __syncthreads();
        gemm44_xw(s_b2, s_x, s_ws, tid);                    __syncthreads();
        load_sm(s_ws, V_sabs + s * Dn * Dn, Dn * Dn, tid); __syncthreads();
        gemm44_xw(s_b3, s_x, s_ws, tid);                    __syncthreads();

        // scores[q][k] = dot(Qx[q],Kx[k])/8, causal/key mask, * pm[q]
        // thread tile: 4 contiguous q rows x 4 strided k rows (k = kr + 13m)
        if (tid < 169) {
            int qp = tid / 13, kr = tid % 13;
            const float* Q0 = s_b1 + qp * 4 * XS;
            const float* K0 = s_b2 + kr * XS;
            float a[4][4];
#pragma unroll
            for (int j = 0; j < 4; j++)
#pragma unroll
                for (int m = 0; m < 4; m++) a[j][m] = 0.0f;
#pragma unroll 4
            for (int d4 = 0; d4 < 16; d4++) {
                float4 qv[4], kv[4];
#pragma unroll
                for (int j = 0; j < 4; j++) qv[j] = *(const float4*)(Q0 + j * XS + d4 * 4);
#pragma unroll
                for (int m = 0; m < 4; m++) kv[m] = *(const float4*)(K0 + m * 13 * XS + d4 * 4);
#pragma unroll
                for (int j = 0; j < 4; j++)
#pragma unroll
                    for (int m = 0; m < 4; m++) {
                        a[j][m] += qv[j].x * kv[m].x;
                        a[j][m] += qv[j].y * kv[m].y;
                        a[j][m] += qv[j].z * kv[m].z;
                        a[j][m] += qv[j].w * kv[m].w;
                    }
            }
#pragma unroll
            for (int j = 0; j < 4; j++) {
                int q = qp * 4 + j;
#pragma unroll
                for (int m = 0; m < 4; m++) {
                    int k = kr + 13 * m;
                    float v;
                    if (q >= Ln || k >= Ln) v = 0.0f;
                    else {
                        v = a[j][m] * 0.125f;
                        if (k > q) v = NEGV;
                        if (s_pm[k] == 0.0f) v = NEGV;
                        v *= s_pm[q];
                    }
                    s_sc[q * SCS + k] = v;
                }
            }
        }
        __syncthreads();

        // att = scores @ Vx + x -> b2 (Kx dead), then LN
        if (tid < 208) {
            int rp = tid >> 4, c4 = tid & 15;
            float a[4][4];
#pragma unroll
            for (int j = 0; j < 4; j++)
#pragma unroll
                for (int i = 0; i < 4; i++) a[j][i] = 0.0f;
            core52(s_sc + rp * 4 * SCS, SCS, s_b3, c4, a);
#pragma unroll
            for (int j = 0; j < 4; j++) {
                int l = rp * 4 + j;
                const float* xr = s_x + l * XS + c4 * 4;
                *(float4*)(s_b2 + l * XS + c4 * 4) =
                    make_float4(a[j][0] + xr[0], a[j][1] + xr[1],
                                a[j][2] + xr[2], a[j][3] + xr[3]);
            }
        }
        __syncthreads();
        ln_rows(s_b2, warp, lane);   // att in b2
        __syncthreads();

        // h = relu(c1_w @ att + c1_b) -> b1
        stage_w52(s_ws, c1_w + s * Ln * Ln, s_cb, c1_b + s * Ln, tid); __syncthreads();
        if (tid < 208) {
            int rp = tid >> 4, c4 = tid & 15;
            float a[4][4];
#pragma unroll
            for (int j = 0; j < 4; j++)
#pragma unroll
                for (int i = 0; i < 4; i++) a[j][i] = 0.0f;
            core52(s_ws + rp * 4 * Lp, Lp, s_b2, c4, a);
#pragma unroll
            for (int j = 0; j < 4; j++) {
                int l = rp * 4 + j;
                float4 r;
                if (l < Ln) {
                    float bb = s_cb[l];
                    r = make_float4(fmaxf(a[j][0] + bb, 0.f), fmaxf(a[j][1] + bb, 0.f),
                                    fmaxf(a[j][2] + bb, 0.f), fmaxf(a[j][3] + bb, 0.f));
                } else r = make_float4(0.f, 0.f, 0.f, 0.f);
                *(float4*)(s_b1 + l * XS + c4 * 4) = r;
            }
        }
        __syncthreads();

        // ff = c2_w @ h + c2_b + att, * pm -> x, then LN
        stage_w52(s_ws, c2_w + s * Ln * Ln, s_cb, c2_b + s * Ln, tid); __syncthreads();
        if (tid < 208) {
            int rp = tid >> 4, c4 = tid & 15;
            float a[4][4];
#pragma unroll
            for (int j = 0; j < 4; j++)
#pragma unroll
                for (int i = 0; i < 4; i++) a[j][i] = 0.0f;
            core52(s_ws + rp * 4 * Lp, Lp, s_b1, c4, a);
#pragma unroll
            for (int j = 0; j < 4; j++) {
                int l = rp * 4 + j;
                float4 r;
                if (l < Ln) {
                    float bb = s_cb[l], pmv = s_pm[l];
                    const float* at = s_b2 + l * XS + c4 * 4;
                    r = make_float4((a[j][0] + bb + at[0]) * pmv, (a[j][1] + bb + at[1]) * pmv,
                                    (a[j][2] + bb + at[2]) * pmv, (a[j][3] + bb + at[3]) * pmv);
                } else r = make_float4(0.f, 0.f, 0.f, 0.f);
                *(float4*)(s_x + l * XS + c4 * 4) = r;
            }
        }
        __syncthreads();
        ln_rows(s_x, warp, lane);
        __syncthreads();
    }

    // ---- LBA head: Kx = inputs @ K_lba (b1), Vx = inputs @ V_lba (b2) ----
    load_sm(s_ws, K_lba, Dn * Dn, tid); __syncthreads();
    gemm44_xw(s_b1, s_in, s_ws, tid);    __syncthreads();
    load_sm(s_ws, V_lba, Dn * Dn, tid); __syncthreads();
    gemm44_xw(s_b2, s_in, s_ws, tid);    __syncthreads();

    // sc[l] = dot(query, Kx[l]); key-mask
    for (int l = warp; l < Ln; l += 8) {
        float r = s_qv[lane] * s_b1[l * XS + lane] + s_qv[lane + 32] * s_b1[l * XS + lane + 32];
        r = wredsum(r);
        if (s_pm[l] == 0.0f) r = NEGV;
        if (lane == 0) s_scq[l] = r;
    }
    __syncthreads();

    // softmax over L (warp 0)
    if (warp == 0) {
        float v0 = (lane < Ln) ? s_scq[lane] : -3.4e38f;
        float v1 = (lane + 32 < Ln) ? s_scq[lane + 32] : -3.4e38f;
        float m = wredmax(fmaxf(v0, v1));
        float e0 = (lane < Ln) ? expf(v0 - m) : 0.0f;
        float e1 = (lane + 32 < Ln) ? expf(v1 - m) : 0.0f;
        float ssum = wredsum(e0 + e1);
        float inv = 1.0f / ssum;
        if (lane < Ln) s_scq[lane] = e0 * inv;
        if (lane + 32 < Ln) s_scq[lane + 32] = e1 * inv;
    }
    __syncthreads();

    // glo[d] = sum_l p[l] * Vx[l][d]
    if (tid < Dn) {
        float a = 0.0f;
#pragma unroll 5
        for (int l = 0; l < Ln; l++) a += s_scq[l] * s_b2[l * XS + tid];
        s_glo[tid] = a;
    }
    __syncthreads();

    // LN -> MLP -> residual -> LN -> gfin; a_glo = dot(gfin, w1)+bias (warp 0)
    if (warp == 0) {
        float g0 = s_glo[lane], g1 = s_glo[lane + 32];
        float mu = wredsum(g0 + g1) * (1.0f / Dn);
        g0 -= mu; g1 -= mu;
        float var = wredsum(g0 * g0 + g1 * g1) * (1.0f / Dn);
        float inv = rsqrtf(var + 1e-8f);
        g0 *= inv; g1 *= inv;
        float w1v = l1_w[0], b1v = l1_b[0], w2v = l2_w[0], b2v = l2_b[0];
        float h0 = fmaxf(w1v * g0 + b1v, 0.0f);
        float h1 = fmaxf(w1v * g1 + b1v, 0.0f);
        float f0 = w2v * h0 + b2v + g0;
        float f1 = w2v * h1 + b2v + g1;
        mu = wredsum(f0 + f1) * (1.0f / Dn);
        f0 -= mu; f1 -= mu;
        var = wredsum(f0 * f0 + f1 * f1) * (1.0f / Dn);
        inv = rsqrtf(var + 1e-8f);
        f0 *= inv; f1 *= inv;
        s_gf[lane] = f0; s_gf[lane + 32] = f1;
        float r = wredsum(f0 * s_gw[64 + lane] + f1 * s_gw[96 + lane]);
        if (lane == 0) s_ms[0] = r + gated_bias[0];
    }

    // a_ie[l] = dot(ie_raw[l], w0)
    for (int l = warp; l < Ln; l += 8) {
        int idx = user_items[b * Ln + l];
        float r = item_embedding[idx * Dn + lane] * s_gw[lane]
                + item_embedding[idx * Dn + lane + 32] * s_gw[lane + 32];
        r = wredsum(r);
        if (lane == 0) s_aie[l] = r;
    }
    __syncthreads();

    // ---- gating + output LN + dot with pos_e / neg_e ----
    float base_glo = s_ms[0];
    float gf0 = s_gf[lane], gf1 = s_gf[lane + 32];
    for (int l = warp; l < Ln; l += 8) {
        float xv0 = s_x[l * XS + lane], xv1 = s_x[l * XS + lane + 32];
        float pmv = s_pm[l];
        float base = s_aie[l] + base_glo;
#pragma unroll
        for (int br = 0; br < 2; br++) {
            const int* items = br ? neg_items : pos_items;
            int idx = items[b * Ln + l];
            float m0 = item_embedding[idx * Dn + lane];
            float m1 = item_embedding[idx * Dn + lane + 32];
            float dm = wredsum(m0 * s_gw[128 + lane] + m1 * s_gw[160 + lane]);
            float logit = base + dm;
            float g = sigm(sigm(logit));
            float o0 = (xv0 * g + gf0 * (1.0f - g)) * pmv;
            float o1 = (xv1 * g + gf1 * (1.0f - g)) * pmv;
            float mu = wredsum(o0 + o1) * (1.0f / Dn);
            o0 -= mu; o1 -= mu;
            float var = wredsum(o0 * o0 + o1 * o1) * (1.0f / Dn);
            float inv = rsqrtf(var + 1e-8f);
            float r = wredsum((o0 * m0 + o1 * m1) * inv);
            if (lane == 0) out[br * (Bn * Ln) + b * Ln + l] = r;
        }
    }
}

extern "C" void kernel_launch(void* const* d_in, const int* in_sizes, int n_in,
                              void* d_out, int out_size) {
    const int*   user_items     = (const int*)d_in[0];
    const int*   pos_items      = (const int*)d_in[1];
    const int*   neg_items      = (const int*)d_in[2];
    const float* padding_mask   = (const float*)d_in[3];
    const float* item_embedding = (const float*)d_in[4];
    const float* pos_embedding  = (const float*)d_in[5];
    const float* Q_sabs         = (const float*)d_in[6];
    const float* K_sabs         = (const float*)d_in[7];
    const float* V_sabs         = (const float*)d_in[8];
    const float* c1_w           = (const float*)d_in[9];
    const float* c1_b           = (const float*)d_in[10];
    const float* c2_w           = (const float*)d_in[11];
    const float* c2_b           = (const float*)d_in[12];
    const float* query_item     = (const float*)d_in[13];
    const float* K_lba          = (const float*)d_in[14];
    const float* V_lba          = (const float*)d_in[15];
    const float* l1_w           = (const float*)d_in[16];
    const float* l1_b           = (const float*)d_in[17];
    const float* l2_w           = (const float*)d_in[18];
    const float* l2_b           = (const float*)d_in[19];
    const float* gated_weight   = (const float*)d_in[20];
    const float* gated_bias     = (const float*)d_in[21];

    size_t smem = SMEM_FLOATS * sizeof(float);
    cudaFuncSetAttribute(fissa_kernel, cudaFuncAttributeMaxDynamicSharedMemorySize, (int)smem);
    fissa_kernel<<<Bn, NT, smem>>>(
        user_items, pos_items, neg_items, padding_mask, item_embedding, pos_embedding,
        Q_sabs, K_sabs, V_sabs, c1_w, c1_b, c2_w, c2_b, query_item, K_lba, V_lba,
        l1_w, l1_b, l2_w, l2_b, gated_weight, gated_bias, (float*)d_out);
}

// round 4
// speedup vs baseline: 1.3949x; 1.1899x over previous
#include <cuda_runtime.h>

#define Bn 1024
#define Ln 50
#define Lp 52      // padded row count
#define Dn 64
#define Sn 2
#define XS 68      // row stride (floats) for Lp x D activation arrays (16B-aligned, 4*XS%32==16)
#define SCS 52     // row stride for the padded 52x52 score matrix
#define NT 256
#define NEGV -4294967296.0f   // float(-2**32+1) after fp32 rounding (matches JAX)

// ---- shared memory layout (float offsets) ----
// act buffers: x, b1, b2, b3 (Lp*XS = 3536 each)
#define O_X     0
#define O_B1    3536
#define O_B2    7072
#define O_B3    10608
#define O_WS    14144   // weight staging (64x64) UNION scores (52x52=2704) -- timeline disjoint
#define O_CB    18240   // staged bias (52)
#define O_PM    18292   // padding mask (52)
#define O_QV    18344   // query vector (64)
#define O_SCQ   18408   // lba scores / softmax probs (64)
#define O_GLO   18472   // glo (64)
#define O_GFIN  18536   // final glo (64)
#define O_GW    18600   // gated_weight (192)
#define O_AIE   18792   // dot(ie, w0) per row (56)
#define O_MISC  18848   // scalars (16)
#define SMEM_FLOATS 18864   // 75.456 KB -> 3 CTAs/SM

__device__ __forceinline__ float wredsum(float v) {
#pragma unroll
    for (int o = 16; o; o >>= 1) v += __shfl_xor_sync(0xffffffffu, v, o);
    return v;
}
__device__ __forceinline__ float wredmax(float v) {
#pragma unroll
    for (int o = 16; o; o >>= 1) v = fmaxf(v, __shfl_xor_sync(0xffffffffu, v, o));
    return v;
}
__device__ __forceinline__ float sigm(float x) { return 1.0f / (1.0f + expf(-x)); }

// in-place LayerNorm of rows 0..49 (D cols, stride XS); one warp per row
__device__ __forceinline__ void ln_rows(float* m, int warp, int lane) {
    for (int l = warp; l < Ln; l += 8) {
        float v0 = m[l * XS + lane], v1 = m[l * XS + lane + 32];
        float mu = wredsum(v0 + v1) * (1.0f / Dn);
        v0 -= mu; v1 -= mu;
        float var = wredsum(v0 * v0 + v1 * v1) * (1.0f / Dn);
        float inv = rsqrtf(var + 1e-8f);
        m[l * XS + lane] = v0 * inv;
        m[l * XS + lane + 32] = v1 * inv;
    }
}

// out(Lp x D, stride XS) = xin(Lp x D, stride XS) @ w(DxD, row-major stride Dn)
// 4 rows x 4 cols per thread, 4-deep k unroll, all LDS.128.
__device__ __forceinline__ void gemm44_xw(float* __restrict__ out, const float* __restrict__ xin,
                                          const float* __restrict__ w, int tid) {
    if (tid < 208) {                 // 13 row-blocks x 16 col-blocks
        int rp = tid >> 4, c4 = tid & 15;
        const float* x0 = xin + rp * 4 * XS;
        float a[4][4];
#pragma unroll
        for (int j = 0; j < 4; j++)
#pragma unroll
            for (int i = 0; i < 4; i++) a[j][i] = 0.0f;
#pragma unroll 4
        for (int k4 = 0; k4 < 16; k4++) {
            float4 xv[4];
#pragma unroll
            for (int j = 0; j < 4; j++)
                xv[j] = *(const float4*)(x0 + j * XS + k4 * 4);
#pragma unroll
            for (int kk = 0; kk < 4; kk++) {
                float4 wv = *(const float4*)(w + (k4 * 4 + kk) * Dn + c4 * 4);
#pragma unroll
                for (int j = 0; j < 4; j++) {
                    float xk = ((const float*)&xv[j])[kk];
                    a[j][0] += xk * wv.x; a[j][1] += xk * wv.y;
                    a[j][2] += xk * wv.z; a[j][3] += xk * wv.w;
                }
            }
        }
#pragma unroll
        for (int j = 0; j < 4; j++) {
            *(float4*)(out + (rp * 4 + j) * XS + c4 * 4) =
                make_float4(a[j][0], a[j][1], a[j][2], a[j][3]);
        }
    }
}

// core: acc += A(4 rows, stride astr, inner 52) x B(52 x D, stride XS), cols c4*4..+3
__device__ __forceinline__ void core52(const float* __restrict__ A0, int astr,
                                       const float* __restrict__ Bm, int c4, float a[4][4]) {
#pragma unroll 4
    for (int k4 = 0; k4 < 13; k4++) {
        float4 wv[4];
#pragma unroll
        for (int j = 0; j < 4; j++)
            wv[j] = *(const float4*)(A0 + j * astr + k4 * 4);
#pragma unroll
        for (int kk = 0; kk < 4; kk++) {
            float4 bv = *(const float4*)(Bm + (k4 * 4 + kk) * XS + c4 * 4);
#pragma unroll
            for (int j = 0; j < 4; j++) {
                float wk = ((const float*)&wv[j])[kk];
                a[j][0] += wk * bv.x; a[j][1] += wk * bv.y;
                a[j][2] += wk * bv.z; a[j][3] += wk * bv.w;
            }
        }
    }
}

__device__ __forceinline__ void load_sm(float* dst, const float* src, int n, int tid) {
    for (int i = tid; i < n; i += NT) dst[i] = src[i];
}

// stage 50x50 weight -> 52x52 zero-padded, plus 50-entry bias -> 52 padded
__device__ __forceinline__ void stage_w52(float* dst, const float* src,
                                          float* cb_dst, const float* cb_src, int tid) {
    for (int i = tid; i < Lp * Lp; i += NT) {
        int r = i / Lp, c = i % Lp;
        dst[i] = (r < Ln && c < Ln) ? src[r * Ln + c] : 0.0f;
    }
    if (tid < Lp) cb_dst[tid] = (tid < Ln) ? cb_src[tid] : 0.0f;
}

// embed + pos + mask + LN -> dst (rows 0..49); pad rows assumed pre-zeroed
__device__ __forceinline__ void build_inputs(float* dst, const int* __restrict__ user_items,
                                             const float* __restrict__ item_embedding,
                                             const float* __restrict__ pos_embedding,
                                             const float* s_pm, int b, int warp, int lane) {
    for (int l = warp; l < Ln; l += 8) {
        int idx = user_items[b * Ln + l];
        float v0 = item_embedding[idx * Dn + lane]      + pos_embedding[l * Dn + lane];
        float v1 = item_embedding[idx * Dn + lane + 32] + pos_embedding[l * Dn + lane + 32];
        float pmv = s_pm[l];
        v0 *= pmv; v1 *= pmv;
        float mu = wredsum(v0 + v1) * (1.0f / Dn);
        v0 -= mu; v1 -= mu;
        float var = wredsum(v0 * v0 + v1 * v1) * (1.0f / Dn);
        float inv = rsqrtf(var + 1e-8f);
        dst[l * XS + lane] = v0 * inv;
        dst[l * XS + lane + 32] = v1 * inv;
    }
}

__global__ void __launch_bounds__(NT, 3) fissa_kernel(
    const int* __restrict__ user_items, const int* __restrict__ pos_items,
    const int* __restrict__ neg_items, const float* __restrict__ padding_mask,
    const float* __restrict__ item_embedding, const float* __restrict__ pos_embedding,
    const float* __restrict__ Q_sabs, const float* __restrict__ K_sabs,
    const float* __restrict__ V_sabs, const float* __restrict__ c1_w,
    const float* __restrict__ c1_b, const float* __restrict__ c2_w,
    const float* __restrict__ c2_b, const float* __restrict__ query_item,
    const float* __restrict__ K_lba, const float* __restrict__ V_lba,
    const float* __restrict__ l1_w, const float* __restrict__ l1_b,
    const float* __restrict__ l2_w, const float* __restrict__ l2_b,
    const float* __restrict__ gated_weight, const float* __restrict__ gated_bias,
    float* __restrict__ out)
{
    extern __shared__ float sm[];
    float* s_x   = sm + O_X;
    float* s_b1  = sm + O_B1;
    float* s_b2  = sm + O_B2;
    float* s_b3  = sm + O_B3;
    float* s_ws  = sm + O_WS;
    float* s_sc  = sm + O_WS;   // scores alias the weight-staging buffer
    float* s_cb  = sm + O_CB;
    float* s_pm  = sm + O_PM;
    float* s_qv  = sm + O_QV;
    float* s_scq = sm + O_SCQ;
    float* s_glo = sm + O_GLO;
    float* s_gf  = sm + O_GFIN;
    float* s_gw  = sm + O_GW;
    float* s_aie = sm + O_AIE;
    float* s_ms  = sm + O_MISC;

    const int b = blockIdx.x;
    const int tid = threadIdx.x;
    const int lane = tid & 31;
    const int warp = tid >> 5;

    if (tid < Lp)  s_pm[tid] = (tid < Ln) ? padding_mask[b * Ln + tid] : 0.0f;
    if (tid < Dn)  s_qv[tid] = query_item[tid];
    if (tid < 192) s_gw[tid] = gated_weight[tid];
    // zero padded rows 50,51 of x and b3 (b3 gets inputs rebuilt for LBA later)
    if (tid < 2 * XS) { s_x[Ln * XS + tid] = 0.0f; s_b3[Ln * XS + tid] = 0.0f; }
    __syncthreads();

    build_inputs(s_x, user_items, item_embedding, pos_embedding, s_pm, b, warp, lane);
    __syncthreads();

    // ---- transformer layers ----
    for (int s = 0; s < Sn; s++) {
        load_sm(s_ws, Q_sabs + s * Dn * Dn, Dn * Dn, tid); __syncthreads();
        gemm44_xw(s_b1, s_x, s_ws, tid);                    __syncthreads();
        load_sm(s_ws, K_sabs + s * Dn * Dn, Dn * Dn, tid); __syncthreads();
        gemm44_xw(s_b2, s_x, s_ws, tid);                    __syncthreads();
        load_sm(s_ws, V_sabs + s * Dn * Dn, Dn * Dn, tid); __syncthreads();
        gemm44_xw(s_b3, s_x, s_ws, tid);                    __syncthreads();

        // scores[q][k] = dot(Qx[q],Kx[k])/8, causal/key mask, * pm[q] -> s_sc (aliases ws; V weight dead)
        if (tid < 169) {
            int qp = tid / 13, kr = tid % 13;
            const float* Q0 = s_b1 + qp * 4 * XS;
            const float* K0 = s_b2 + kr * XS;
            float a[4][4];
#pragma unroll
            for (int j = 0; j < 4; j++)
#pragma unroll
                for (int m = 0; m < 4; m++) a[j][m] = 0.0f;
#pragma unroll 4
            for (int d4 = 0; d4 < 16; d4++) {
                float4 qv[4], kv[4];
#pragma unroll
                for (int j = 0; j < 4; j++) qv[j] = *(const float4*)(Q0 + j * XS + d4 * 4);
#pragma unroll
                for (int m = 0; m < 4; m++) kv[m] = *(const float4*)(K0 + m * 13 * XS + d4 * 4);
#pragma unroll
                for (int j = 0; j < 4; j++)
#pragma unroll
                    for (int m = 0; m < 4; m++) {
                        a[j][m] += qv[j].x * kv[m].x;
                        a[j][m] += qv[j].y * kv[m].y;
                        a[j][m] += qv[j].z * kv[m].z;
                        a[j][m] += qv[j].w * kv[m].w;
                    }
            }
#pragma unroll
            for (int j = 0; j < 4; j++) {
                int q = qp * 4 + j;
#pragma unroll
                for (int m = 0; m < 4; m++) {
                    int k = kr + 13 * m;
                    float v;
                    if (q >= Ln || k >= Ln) v = 0.0f;
                    else {
                        v = a[j][m] * 0.125f;
                        if (k > q) v = NEGV;
                        if (s_pm[k] == 0.0f) v = NEGV;
                        v *= s_pm[q];
                    }
                    s_sc[q * SCS + k] = v;
                }
            }
        }
        __syncthreads();

        // att = scores @ Vx + x -> b2 (Kx dead), then LN
        if (tid < 208) {
            int rp = tid >> 4, c4 = tid & 15;
            float a[4][4];
#pragma unroll
            for (int j = 0; j < 4; j++)
#pragma unroll
                for (int i = 0; i < 4; i++) a[j][i] = 0.0f;
            core52(s_sc + rp * 4 * SCS, SCS, s_b3, c4, a);
#pragma unroll
            for (int j = 0; j < 4; j++) {
                int l = rp * 4 + j;
                const float* xr = s_x + l * XS + c4 * 4;
                *(float4*)(s_b2 + l * XS + c4 * 4) =
                    make_float4(a[j][0] + xr[0], a[j][1] + xr[1],
                                a[j][2] + xr[2], a[j][3] + xr[3]);
            }
        }
        __syncthreads();
        ln_rows(s_b2, warp, lane);   // att in b2
        __syncthreads();

        // h = relu(c1_w @ att + c1_b) -> b1   (scores dead; stage c1 into ws)
        stage_w52(s_ws, c1_w + s * Ln * Ln, s_cb, c1_b + s * Ln, tid); __syncthreads();
        if (tid < 208) {
            int rp = tid >> 4, c4 = tid & 15;
            float a[4][4];
#pragma unroll
            for (int j = 0; j < 4; j++)
#pragma unroll
                for (int i = 0; i < 4; i++) a[j][i] = 0.0f;
            core52(s_ws + rp * 4 * Lp, Lp, s_b2, c4, a);
#pragma unroll
            for (int j = 0; j < 4; j++) {
                int l = rp * 4 + j;
                float4 r;
                if (l < Ln) {
                    float bb = s_cb[l];
                    r = make_float4(fmaxf(a[j][0] + bb, 0.f), fmaxf(a[j][1] + bb, 0.f),
                                    fmaxf(a[j][2] + bb, 0.f), fmaxf(a[j][3] + bb, 0.f));
                } else r = make_float4(0.f, 0.f, 0.f, 0.f);
                *(float4*)(s_b1 + l * XS + c4 * 4) = r;
            }
        }
        __syncthreads();

        // ff = c2_w @ h + c2_b + att, * pm -> x, then LN
        stage_w52(s_ws, c2_w + s * Ln * Ln, s_cb, c2_b + s * Ln, tid); __syncthreads();
        if (tid < 208) {
            int rp = tid >> 4, c4 = tid & 15;
            float a[4][4];
#pragma unroll
            for (int j = 0; j < 4; j++)
#pragma unroll
                for (int i = 0; i < 4; i++) a[j][i] = 0.0f;
            core52(s_ws + rp * 4 * Lp, Lp, s_b1, c4, a);
#pragma unroll
            for (int j = 0; j < 4; j++) {
                int l = rp * 4 + j;
                float4 r;
                if (l < Ln) {
                    float bb = s_cb[l], pmv = s_pm[l];
                    const float* at = s_b2 + l * XS + c4 * 4;
                    r = make_float4((a[j][0] + bb + at[0]) * pmv, (a[j][1] + bb + at[1]) * pmv,
                                    (a[j][2] + bb + at[2]) * pmv, (a[j][3] + bb + at[3]) * pmv);
                } else r = make_float4(0.f, 0.f, 0.f, 0.f);
                *(float4*)(s_x + l * XS + c4 * 4) = r;
            }
        }
        __syncthreads();
        ln_rows(s_x, warp, lane);
        __syncthreads();
    }

    // ---- rebuild post-LN inputs into b3 (cheap; embeddings are L2-resident) ----
    build_inputs(s_b3, user_items, item_embedding, pos_embedding, s_pm, b, warp, lane);
    __syncthreads();

    // ---- LBA head: Kx = inputs @ K_lba (b1), Vx = inputs @ V_lba (b2) ----
    load_sm(s_ws, K_lba, Dn * Dn, tid); __syncthreads();
    gemm44_xw(s_b1, s_b3, s_ws, tid);    __syncthreads();
    load_sm(s_ws, V_lba, Dn * Dn, tid); __syncthreads();
    gemm44_xw(s_b2, s_b3, s_ws, tid);    __syncthreads();

    // sc[l] = dot(query, Kx[l]); key-mask
    for (int l = warp; l < Ln; l += 8) {
        float r = s_qv[lane] * s_b1[l * XS + lane] + s_qv[lane + 32] * s_b1[l * XS + lane + 32];
        r = wredsum(r);
        if (s_pm[l] == 0.0f) r = NEGV;
        if (lane == 0) s_scq[l] = r;
    }
    __syncthreads();

    // softmax over L (warp 0)
    if (warp == 0) {
        float v0 = (lane < Ln) ? s_scq[lane] : -3.4e38f;
        float v1 = (lane + 32 < Ln) ? s_scq[lane + 32] : -3.4e38f;
        float m = wredmax(fmaxf(v0, v1));
        float e0 = (lane < Ln) ? expf(v0 - m) : 0.0f;
        float e1 = (lane + 32 < Ln) ? expf(v1 - m) : 0.0f;
        float ssum = wredsum(e0 + e1);
        float inv = 1.0f / ssum;
        if (lane < Ln) s_scq[lane] = e0 * inv;
        if (lane + 32 < Ln) s_scq[lane + 32] = e1 * inv;
    }
    __syncthreads();

    // glo[d] = sum_l p[l] * Vx[l][d]
    if (tid < Dn) {
        float a = 0.0f;
#pragma unroll 5
        for (int l = 0; l < Ln; l++) a += s_scq[l] * s_b2[l * XS + tid];
        s_glo[tid] = a;
    }
    __syncthreads();

    // LN -> MLP -> residual -> LN -> gfin; a_glo = dot(gfin, w1)+bias (warp 0)
    if (warp == 0) {
        float g0 = s_glo[lane], g1 = s_glo[lane + 32];
        float mu = wredsum(g0 + g1) * (1.0f / Dn);
        g0 -= mu; g1 -= mu;
        float var = wredsum(g0 * g0 + g1 * g1) * (1.0f / Dn);
        float inv = rsqrtf(var + 1e-8f);
        g0 *= inv; g1 *= inv;
        float w1v = l1_w[0], b1v = l1_b[0], w2v = l2_w[0], b2v = l2_b[0];
        float h0 = fmaxf(w1v * g0 + b1v, 0.0f);
        float h1 = fmaxf(w1v * g1 + b1v, 0.0f);
        float f0 = w2v * h0 + b2v + g0;
        float f1 = w2v * h1 + b2v + g1;
        mu = wredsum(f0 + f1) * (1.0f / Dn);
        f0 -= mu; f1 -= mu;
        var = wredsum(f0 * f0 + f1 * f1) * (1.0f / Dn);
        inv = rsqrtf(var + 1e-8f);
        f0 *= inv; f1 *= inv;
        s_gf[lane] = f0; s_gf[lane + 32] = f1;
        float r = wredsum(f0 * s_gw[64 + lane] + f1 * s_gw[96 + lane]);
        if (lane == 0) s_ms[0] = r + gated_bias[0];
    }

    // a_ie[l] = dot(ie_raw[l], w0)
    for (int l = warp; l < Ln; l += 8) {
        int idx = user_items[b * Ln + l];
        float r = item_embedding[idx * Dn + lane] * s_gw[lane]
                + item_embedding[idx * Dn + lane + 32] * s_gw[lane + 32];
        r = wredsum(r);
        if (lane == 0) s_aie[l] = r;
    }
    __syncthreads();

    // ---- gating + output LN + dot with pos_e / neg_e ----
    float base_glo = s_ms[0];
    float gf0 = s_gf[lane], gf1 = s_gf[lane + 32];
    for (int l = warp; l < Ln; l += 8) {
        float xv0 = s_x[l * XS + lane], xv1 = s_x[l * XS + lane + 32];
        float pmv = s_pm[l];
        float base = s_aie[l] + base_glo;
#pragma unroll
        for (int br = 0; br < 2; br++) {
            const int* items = br ? neg_items : pos_items;
            int idx = items[b * Ln + l];
            float m0 = item_embedding[idx * Dn + lane];
            float m1 = item_embedding[idx * Dn + lane + 32];
            float dm = wredsum(m0 * s_gw[128 + lane] + m1 * s_gw[160 + lane]);
            float logit = base + dm;
            float g = sigm(sigm(logit));
            float o0 = (xv0 * g + gf0 * (1.0f - g)) * pmv;
            float o1 = (xv1 * g + gf1 * (1.0f - g)) * pmv;
            float mu = wredsum(o0 + o1) * (1.0f / Dn);
            o0 -= mu; o1 -= mu;
            float var = wredsum(o0 * o0 + o1 * o1) * (1.0f / Dn);
            float inv = rsqrtf(var + 1e-8f);
            float r = wredsum((o0 * m0 + o1 * m1) * inv);
            if (lane == 0) out[br * (Bn * Ln) + b * Ln + l] = r;
        }
    }
}

extern "C" void kernel_launch(void* const* d_in, const int* in_sizes, int n_in,
                              void* d_out, int out_size) {
    const int*   user_items     = (const int*)d_in[0];
    const int*   pos_items      = (const int*)d_in[1];
    const int*   neg_items      = (const int*)d_in[2];
    const float* padding_mask   = (const float*)d_in[3];
    const float* item_embedding = (const float*)d_in[4];
    const float* pos_embedding  = (const float*)d_in[5];
    const float* Q_sabs         = (const float*)d_in[6];
    const float* K_sabs         = (const float*)d_in[7];
    const float* V_sabs         = (const float*)d_in[8];
    const float* c1_w           = (const float*)d_in[9];
    const float* c1_b           = (const float*)d_in[10];
    const float* c2_w           = (const float*)d_in[11];
    const float* c2_b           = (const float*)d_in[12];
    const float* query_item     = (const float*)d_in[13];
    const float* K_lba          = (const float*)d_in[14];
    const float* V_lba          = (const float*)d_in[15];
    const float* l1_w           = (const float*)d_in[16];
    const float* l1_b           = (const float*)d_in[17];
    const float* l2_w           = (const float*)d_in[18];
    const float* l2_b           = (const float*)d_in[19];
    const float* gated_weight   = (const float*)d_in[20];
    const float* gated_bias     = (const float*)d_in[21];

    size_t smem = SMEM_FLOATS * sizeof(float);
    cudaFuncSetAttribute(fissa_kernel, cudaFuncAttributeMaxDynamicSharedMemorySize, (int)smem);
    fissa_kernel<<<Bn, NT, smem>>>(
        user_items, pos_items, neg_items, padding_mask, item_embedding, pos_embedding,
        Q_sabs, K_sabs, V_sabs, c1_w, c1_b, c2_w, c2_b, query_item, K_lba, V_lba,
        l1_w, l1_b, l2_w, l2_b, gated_weight, gated_bias, (float*)d_out);
}

// round 6
// speedup vs baseline: 1.6906x; 1.2120x over previous
#include <cuda_runtime.h>

#define Bn 1024
#define Ln 50
#define Lp 52      // padded row count
#define Dn 64
#define Sn 2
#define XS 68      // row stride (floats) for Lp x D activation arrays (16B-aligned, 4*XS%32==16)
#define SCS 52     // row stride for the padded 52x52 score matrix
#define NT 256
#define NEGV -4294967296.0f   // float(-2**32+1) after fp32 rounding (matches JAX)

// ---- shared memory layout (float offsets) ----
// act buffers: x, b1, b2 (Lp*XS = 3536 each); ws = scores UNION staged 52x52 c-weights
#define O_X     0
#define O_B1    3536
#define O_B2    7072
#define O_WS    10608   // 52x52 = 2704
#define O_CB    13312   // staged bias (52)
#define O_PM    13364   // padding mask (52)
#define O_QV    13416   // query vector (64)
#define O_SCQ   13480   // lba scores / softmax probs (64)
#define O_GLO   13544   // glo (64)
#define O_GFIN  13608   // final glo (64)
#define O_GW    13672   // gated_weight (192)
#define O_AIE   13864   // dot(ie, w0) per row (56)
#define O_MISC  13920   // scalars (16)
#define SMEM_FLOATS 13936   // 55.74 KB -> 4 CTAs/SM

__device__ __forceinline__ float wredsum(float v) {
#pragma unroll
    for (int o = 16; o; o >>= 1) v += __shfl_xor_sync(0xffffffffu, v, o);
    return v;
}
__device__ __forceinline__ float wredmax(float v) {
#pragma unroll
    for (int o = 16; o; o >>= 1) v = fmaxf(v, __shfl_xor_sync(0xffffffffu, v, o));
    return v;
}
__device__ __forceinline__ float sigm(float x) { return 1.0f / (1.0f + expf(-x)); }

// in-place LayerNorm of rows 0..49 (D cols, stride XS); one warp per row
__device__ __forceinline__ void ln_rows(float* m, int warp, int lane) {
    for (int l = warp; l < Ln; l += 8) {
        float v0 = m[l * XS + lane], v1 = m[l * XS + lane + 32];
        float mu = wredsum(v0 + v1) * (1.0f / Dn);
        v0 -= mu; v1 -= mu;
        float var = wredsum(v0 * v0 + v1 * v1) * (1.0f / Dn);
        float inv = rsqrtf(var + 1e-8f);
        m[l * XS + lane] = v0 * inv;
        m[l * XS + lane + 32] = v1 * inv;
    }
}

// out(Lp x D, stride XS) = xin(Lp x D, stride XS) @ w(DxD GLOBAL, row-major stride Dn)
// 4 rows x 4 cols per thread, 4-deep k unroll; x via LDS.128, w via LDG.128 (L1/L2-resident).
__device__ __forceinline__ void gemm44_xw(float* __restrict__ out, const float* __restrict__ xin,
                                          const float* __restrict__ w, int tid) {
    if (tid < 208) {                 // 13 row-blocks x 16 col-blocks
        int rp = tid >> 4, c4 = tid & 15;
        const float* x0 = xin + rp * 4 * XS;
        const float4* wp = (const float4*)(w + c4 * 4);   // column tile base, stride Dn/4 float4s
        float a[4][4];
#pragma unroll
        for (int j = 0; j < 4; j++)
#pragma unroll
            for (int i = 0; i < 4; i++) a[j][i] = 0.0f;
#pragma unroll 4
        for (int k4 = 0; k4 < 16; k4++) {
            float4 xv[4];
#pragma unroll
            for (int j = 0; j < 4; j++)
                xv[j] = *(const float4*)(x0 + j * XS + k4 * 4);
#pragma unroll
            for (int kk = 0; kk < 4; kk++) {
                float4 wv = __ldg(wp + (k4 * 4 + kk) * (Dn / 4));
#pragma unroll
                for (int j = 0; j < 4; j++) {
                    float xk = ((const float*)&xv[j])[kk];
                    a[j][0] += xk * wv.x; a[j][1] += xk * wv.y;
                    a[j][2] += xk * wv.z; a[j][3] += xk * wv.w;
                }
            }
        }
#pragma unroll
        for (int j = 0; j < 4; j++) {
            *(float4*)(out + (rp * 4 + j) * XS + c4 * 4) =
                make_float4(a[j][0], a[j][1], a[j][2], a[j][3]);
        }
    }
}

// core: acc += A(4 rows, stride astr, inner 52) x B(52 x D, stride XS), cols c4*4..+3
__device__ __forceinline__ void core52(const float* __restrict__ A0, int astr,
                                       const float* __restrict__ Bm, int c4, float a[4][4]) {
#pragma unroll 4
    for (int k4 = 0; k4 < 13; k4++) {
        float4 wv[4];
#pragma unroll
        for (int j = 0; j < 4; j++)
            wv[j] = *(const float4*)(A0 + j * astr + k4 * 4);
#pragma unroll
        for (int kk = 0; kk < 4; kk++) {
            float4 bv = *(const float4*)(Bm + (k4 * 4 + kk) * XS + c4 * 4);
#pragma unroll
            for (int j = 0; j < 4; j++) {
                float wk = ((const float*)&wv[j])[kk];
                a[j][0] += wk * bv.x; a[j][1] += wk * bv.y;
                a[j][2] += wk * bv.z; a[j][3] += wk * bv.w;
            }
        }
    }
}

// stage 50x50 weight -> 52x52 zero-padded, plus 50-entry bias -> 52 padded
__device__ __forceinline__ void stage_w52(float* dst, const float* src,
                                          float* cb_dst, const float* cb_src, int tid) {
    for (int i = tid; i < Lp * Lp; i += NT) {
        int r = i / Lp, c = i % Lp;
        dst[i] = (r < Ln && c < Ln) ? src[r * Ln + c] : 0.0f;
    }
    if (tid < Lp) cb_dst[tid] = (tid < Ln) ? cb_src[tid] : 0.0f;
}

// embed + pos + mask + LN -> dst (rows 0..49)
__device__ __forceinline__ void build_inputs(float* dst, const int* __restrict__ user_items,
                                             const float* __restrict__ item_embedding,
                                             const float* __restrict__ pos_embedding,
                                             const float* s_pm, int b, int warp, int lane) {
    for (int l = warp; l < Ln; l += 8) {
        int idx = user_items[b * Ln + l];
        float v0 = item_embedding[idx * Dn + lane]      + pos_embedding[l * Dn + lane];
        float v1 = item_embedding[idx * Dn + lane + 32] + pos_embedding[l * Dn + lane + 32];
        float pmv = s_pm[l];
        v0 *= pmv; v1 *= pmv;
        float mu = wredsum(v0 + v1) * (1.0f / Dn);
        v0 -= mu; v1 -= mu;
        float var = wredsum(v0 * v0 + v1 * v1) * (1.0f / Dn);
        float inv = rsqrtf(var + 1e-8f);
        dst[l * XS + lane] = v0 * inv;
        dst[l * XS + lane + 32] = v1 * inv;
    }
}

__global__ void __launch_bounds__(NT, 4) fissa_kernel(
    const int* __restrict__ user_items, const int* __restrict__ pos_items,
    const int* __restrict__ neg_items, const float* __restrict__ padding_mask,
    const float* __restrict__ item_embedding, const float* __restrict__ pos_embedding,
    const float* __restrict__ Q_sabs, const float* __restrict__ K_sabs,
    const float* __restrict__ V_sabs, const float* __restrict__ c1_w,
    const float* __restrict__ c1_b, const float* __restrict__ c2_w,
    const float* __restrict__ c2_b, const float* __restrict__ query_item,
    const float* __restrict__ K_lba, const float* __restrict__ V_lba,
    const float* __restrict__ l1_w, const float* __restrict__ l1_b,
    const float* __restrict__ l2_w, const float* __restrict__ l2_b,
    const float* __restrict__ gated_weight, const float* __restrict__ gated_bias,
    float* __restrict__ out)
{
    extern __shared__ float sm[];
    float* s_x   = sm + O_X;
    float* s_b1  = sm + O_B1;
    float* s_b2  = sm + O_B2;
    float* s_ws  = sm + O_WS;   // scores / staged c-weights (timeline-disjoint)
    float* s_sc  = sm + O_WS;
    float* s_cb  = sm + O_CB;
    float* s_pm  = sm + O_PM;
    float* s_qv  = sm + O_QV;
    float* s_scq = sm + O_SCQ;
    float* s_glo = sm + O_GLO;
    float* s_gf  = sm + O_GFIN;
    float* s_gw  = sm + O_GW;
    float* s_aie = sm + O_AIE;
    float* s_ms  = sm + O_MISC;

    const int b = blockIdx.x;
    const int tid = threadIdx.x;
    const int lane = tid & 31;
    const int warp = tid >> 5;

    if (tid < Lp)  s_pm[tid] = (tid < Ln) ? padding_mask[b * Ln + tid] : 0.0f;
    if (tid < Dn)  s_qv[tid] = query_item[tid];
    if (tid < 192) s_gw[tid] = gated_weight[tid];
    // zero padded rows 50,51 of x
    if (tid < 2 * XS) s_x[Ln * XS + tid] = 0.0f;
    __syncthreads();

    build_inputs(s_x, user_items, item_embedding, pos_embedding, s_pm, b, warp, lane);
    __syncthreads();

    // ---- transformer layers ----
    for (int s = 0; s < Sn; s++) {
        gemm44_xw(s_b1, s_x, Q_sabs + s * Dn * Dn, tid);   __syncthreads();  // Qx -> b1
        gemm44_xw(s_b2, s_x, K_sabs + s * Dn * Dn, tid);   __syncthreads();  // Kx -> b2

        // scores[q][k] = dot(Qx[q],Kx[k])/8, causal/key mask, * pm[q] -> ws
        if (tid < 169) {
            int qp = tid / 13, kr = tid % 13;
            const float* Q0 = s_b1 + qp * 4 * XS;
            const float* K0 = s_b2 + kr * XS;
            float a[4][4];
#pragma unroll
            for (int j = 0; j < 4; j++)
#pragma unroll
                for (int m = 0; m < 4; m++) a[j][m] = 0.0f;
#pragma unroll 4
            for (int d4 = 0; d4 < 16; d4++) {
                float4 qv[4], kv[4];
#pragma unroll
                for (int j = 0; j < 4; j++) qv[j] = *(const float4*)(Q0 + j * XS + d4 * 4);
#pragma unroll
                for (int m = 0; m < 4; m++) kv[m] = *(const float4*)(K0 + m * 13 * XS + d4 * 4);
#pragma unroll
                for (int j = 0; j < 4; j++)
#pragma unroll
                    for (int m = 0; m < 4; m++) {
                        a[j][m] += qv[j].x * kv[m].x;
                        a[j][m] += qv[j].y * kv[m].y;
                        a[j][m] += qv[j].z * kv[m].z;
                        a[j][m] += qv[j].w * kv[m].w;
                    }
            }
#pragma unroll
            for (int j = 0; j < 4; j++) {
                int q = qp * 4 + j;
#pragma unroll
                for (int m = 0; m < 4; m++) {
                    int k = kr + 13 * m;
                    float v;
                    if (q >= Ln || k >= Ln) v = 0.0f;
                    else {
                        v = a[j][m] * 0.125f;
                        if (k > q) v = NEGV;
                        if (s_pm[k] == 0.0f) v = NEGV;
                        v *= s_pm[q];
                    }
                    s_sc[q * SCS + k] = v;
                }
            }
        }
        __syncthreads();

        gemm44_xw(s_b1, s_x, V_sabs + s * Dn * Dn, tid);   __syncthreads();  // Vx -> b1 (Qx dead)

        // att = scores @ Vx + x -> b2 (Kx dead), then LN
        if (tid < 208) {
            int rp = tid >> 4, c4 = tid & 15;
            float a[4][4];
#pragma unroll
            for (int j = 0; j < 4; j++)
#pragma unroll
                for (int i = 0; i < 4; i++) a[j][i] = 0.0f;
            core52(s_sc + rp * 4 * SCS, SCS, s_b1, c4, a);
#pragma unroll
            for (int j = 0; j < 4; j++) {
                int l = rp * 4 + j;
                const float* xr = s_x + l * XS + c4 * 4;
                *(float4*)(s_b2 + l * XS + c4 * 4) =
                    make_float4(a[j][0] + xr[0], a[j][1] + xr[1],
                                a[j][2] + xr[2], a[j][3] + xr[3]);
            }
        }
        __syncthreads();
        ln_rows(s_b2, warp, lane);   // att in b2
        __syncthreads();

        // h = relu(c1_w @ att + c1_b) -> b1   (scores dead; stage c1 into ws)
        stage_w52(s_ws, c1_w + s * Ln * Ln, s_cb, c1_b + s * Ln, tid); __syncthreads();
        if (tid < 208) {
            int rp = tid >> 4, c4 = tid & 15;
            float a[4][4];
#pragma unroll
            for (int j = 0; j < 4; j++)
#pragma unroll
                for (int i = 0; i < 4; i++) a[j][i] = 0.0f;
            core52(s_ws + rp * 4 * Lp, Lp, s_b2, c4, a);
#pragma unroll
            for (int j = 0; j < 4; j++) {
                int l = rp * 4 + j;
                float4 r;
                if (l < Ln) {
                    float bb = s_cb[l];
                    r = make_float4(fmaxf(a[j][0] + bb, 0.f), fmaxf(a[j][1] + bb, 0.f),
                                    fmaxf(a[j][2] + bb, 0.f), fmaxf(a[j][3] + bb, 0.f));
                } else r = make_float4(0.f, 0.f, 0.f, 0.f);
                *(float4*)(s_b1 + l * XS + c4 * 4) = r;
            }
        }
        __syncthreads();

        // ff = c2_w @ h + c2_b + att, * pm -> x, then LN
        stage_w52(s_ws, c2_w + s * Ln * Ln, s_cb, c2_b + s * Ln, tid); __syncthreads();
        if (tid < 208) {
            int rp = tid >> 4, c4 = tid & 15;
            float a[4][4];
#pragma unroll
            for (int j = 0; j < 4; j++)
#pragma unroll
                for (int i = 0; i < 4; i++) a[j][i] = 0.0f;
            core52(s_ws + rp * 4 * Lp, Lp, s_b1, c4, a);
#pragma unroll
            for (int j = 0; j < 4; j++) {
                int l = rp * 4 + j;
                float4 r;
                if (l < Ln) {
                    float bb = s_cb[l], pmv = s_pm[l];
                    const float* at = s_b2 + l * XS + c4 * 4;
                    r = make_float4((a[j][0] + bb + at[0]) * pmv, (a[j][1] + bb + at[1]) * pmv,
                                    (a[j][2] + bb + at[2]) * pmv, (a[j][3] + bb + at[3]) * pmv);
                } else r = make_float4(0.f, 0.f, 0.f, 0.f);
                *(float4*)(s_x + l * XS + c4 * 4) = r;
            }
        }
        __syncthreads();
        ln_rows(s_x, warp, lane);
        __syncthreads();
    }

    // ---- rebuild post-LN inputs into b1 (embeddings L2/L1-resident) ----
    if (tid < 2 * XS) s_b1[Ln * XS + tid] = 0.0f;
    __syncthreads();
    build_inputs(s_b1, user_items, item_embedding, pos_embedding, s_pm, b, warp, lane);
    __syncthreads();

    // ---- LBA head ----
    gemm44_xw(s_b2, s_b1, K_lba, tid);  __syncthreads();   // Kx -> b2

    // sc[l] = dot(query, Kx[l]); key-mask
    for (int l = warp; l < Ln; l += 8) {
        float r = s_qv[lane] * s_b2[l * XS + lane] + s_qv[lane + 32] * s_b2[l * XS + lane + 32];
        r = wredsum(r);
        if (s_pm[l] == 0.0f) r = NEGV;
        if (lane == 0) s_scq[l] = r;
    }
    __syncthreads();

    // softmax over L (warp 0)
    if (warp == 0) {
        float v0 = (lane < Ln) ? s_scq[lane] : -3.4e38f;
        float v1 = (lane + 32 < Ln) ? s_scq[lane + 32] : -3.4e38f;
        float m = wredmax(fmaxf(v0, v1));
        float e0 = (lane < Ln) ? expf(v0 - m) : 0.0f;
        float e1 = (lane + 32 < Ln) ? expf(v1 - m) : 0.0f;
        float ssum = wredsum(e0 + e1);
        float inv = 1.0f / ssum;
        if (lane < Ln) s_scq[lane] = e0 * inv;
        if (lane + 32 < Ln) s_scq[lane + 32] = e1 * inv;
    }
    __syncthreads();

    gemm44_xw(s_b2, s_b1, V_lba, tid);  __syncthreads();   // Vx -> b2 (Kx dead)

    // glo[d] = sum_l p[l] * Vx[l][d]
    if (tid < Dn) {
        float a = 0.0f;
#pragma unroll 5
        for (int l = 0; l < Ln; l++) a += s_scq[l] * s_b2[l * XS + tid];
        s_glo[tid] = a;
    }
    __syncthreads();

    // LN -> MLP -> residual -> LN -> gfin; a_glo = dot(gfin, w1)+bias (warp 0)
    if (warp == 0) {
        float g0 = s_glo[lane], g1 = s_glo[lane + 32];
        float mu = wredsum(g0 + g1) * (1.0f / Dn);
        g0 -= mu; g1 -= mu;
        float var = wredsum(g0 * g0 + g1 * g1) * (1.0f / Dn);
        float inv = rsqrtf(var + 1e-8f);
        g0 *= inv; g1 *= inv;
        float w1v = l1_w[0], b1v = l1_b[0], w2v = l2_w[0], b2v = l2_b[0];
        float h0 = fmaxf(w1v * g0 + b1v, 0.0f);
        float h1 = fmaxf(w1v * g1 + b1v, 0.0f);
        float f0 = w2v * h0 + b2v + g0;
        float f1 = w2v * h1 + b2v + g1;
        mu = wredsum(f0 + f1) * (1.0f / Dn);
        f0 -= mu; f1 -= mu;
        var = wredsum(f0 * f0 + f1 * f1) * (1.0f / Dn);
        inv = rsqrtf(var + 1e-8f);
        f0 *= inv; f1 *= inv;
        s_gf[lane] = f0; s_gf[lane + 32] = f1;
        float r = wredsum(f0 * s_gw[64 + lane] + f1 * s_gw[96 + lane]);
        if (lane == 0) s_ms[0] = r + gated_bias[0];
    }

    // a_ie[l] = dot(ie_raw[l], w0)
    for (int l = warp; l < Ln; l += 8) {
        int idx = user_items[b * Ln + l];
        float r = item_embedding[idx * Dn + lane] * s_gw[lane]
                + item_embedding[idx * Dn + lane + 32] * s_gw[lane + 32];
        r = wredsum(r);
        if (lane == 0) s_aie[l] = r;
    }
    __syncthreads();

    // ---- gating + output LN + dot with pos_e / neg_e ----
    float base_glo = s_ms[0];
    float gf0 = s_gf[lane], gf1 = s_gf[lane + 32];
    for (int l = warp; l < Ln; l += 8) {
        float xv0 = s_x[l * XS + lane], xv1 = s_x[l * XS + lane + 32];
        float pmv = s_pm[l];
        float base = s_aie[l] + base_glo;
#pragma unroll
        for (int br = 0; br < 2; br++) {
            const int* items = br ? neg_items : pos_items;
            int idx = items[b * Ln + l];
            float m0 = item_embedding[idx * Dn + lane];
            float m1 = item_embedding[idx * Dn + lane + 32];
            float dm = wredsum(m0 * s_gw[128 + lane] + m1 * s_gw[160 + lane]);
            float logit = base + dm;
            float g = sigm(sigm(logit));
            float o0 = (xv0 * g + gf0 * (1.0f - g)) * pmv;
            float o1 = (xv1 * g + gf1 * (1.0f - g)) * pmv;
            float mu = wredsum(o0 + o1) * (1.0f / Dn);
            o0 -= mu; o1 -= mu;
            float var = wredsum(o0 * o0 + o1 * o1) * (1.0f / Dn);
            float inv = rsqrtf(var + 1e-8f);
            float r = wredsum((o0 * m0 + o1 * m1) * inv);
            if (lane == 0) out[br * (Bn * Ln) + b * Ln + l] = r;
        }
    }
}

extern "C" void kernel_launch(void* const* d_in, const int* in_sizes, int n_in,
                              void* d_out, int out_size) {
    const int*   user_items     = (const int*)d_in[0];
    const int*   pos_items      = (const int*)d_in[1];
    const int*   neg_items      = (const int*)d_in[2];
    const float* padding_mask   = (const float*)d_in[3];
    const float* item_embedding = (const float*)d_in[4];
    const float* pos_embedding  = (const float*)d_in[5];
    const float* Q_sabs         = (const float*)d_in[6];
    const float* K_sabs         = (const float*)d_in[7];
    const float* V_sabs         = (const float*)d_in[8];
    const float* c1_w           = (const float*)d_in[9];
    const float* c1_b           = (const float*)d_in[10];
    const float* c2_w           = (const float*)d_in[11];
    const float* c2_b           = (const float*)d_in[12];
    const float* query_item     = (const float*)d_in[13];
    const float* K_lba          = (const float*)d_in[14];
    const float* V_lba          = (const float*)d_in[15];
    const float* l1_w           = (const float*)d_in[16];
    const float* l1_b           = (const float*)d_in[17];
    const float* l2_w           = (const float*)d_in[18];
    const float* l2_b           = (const float*)d_in[19];
    const float* gated_weight   = (const float*)d_in[20];
    const float* gated_bias     = (const float*)d_in[21];

    size_t smem = SMEM_FLOATS * sizeof(float);
    cudaFuncSetAttribute(fissa_kernel, cudaFuncAttributeMaxDynamicSharedMemorySize, (int)smem);
    fissa_kernel<<<Bn, NT, smem>>>(
        user_items, pos_items, neg_items, padding_mask, item_embedding, pos_embedding,
        Q_sabs, K_sabs, V_sabs, c1_w, c1_b, c2_w, c2_b, query_item, K_lba, V_lba,
        l1_w, l1_b, l2_w, l2_b, gated_weight, gated_bias, (float*)d_out);
}